// round 11
// baseline (speedup 1.0000x reference)
#include <cuda_runtime.h>
#include <cuda_bf16.h>
#include <math.h>

#define MROWS 8192
#define NCOLS 4096
#define T_ITERS 40
#define NBLK 256               // matvec blocks
#define RPB 32                 // rows per matvec block
#define NCHUNK 32              // rows, processed 1/step
#define ROW_U4 (NCOLS / 8)     // 512 uint4 per bf16 row
#define REDB 64                // reducer slots (last arrivals) = norm partials

// ---------------- device scratch ----------------
__device__ __nv_bfloat16 g_Xb[(size_t)MROWS * NCOLS];  // 67MB bf16 copy of X
__device__ float g_y[3 * NCOLS];
__device__ float g_wpart[NBLK * NCOLS];
__device__ float g_dot[NBLK];
__device__ float g_ss[(T_ITERS + 1) * REDB];
__device__ float g_alpha[T_ITERS];
__device__ int   g_ctr[T_ITERS];

// ---------------- one-time fp32 -> bf16 conversion ----------------
__global__ void __launch_bounds__(256) k_tobf16(const float* __restrict__ X) {
    const float4* X4 = (const float4*)X;
    uint2* out = (uint2*)g_Xb;
    size_t base = (size_t)blockIdx.x * 1024 + threadIdx.x;
#pragma unroll
    for (int i = 0; i < 4; i++) {
        size_t idx = base + (size_t)i * 256;
        float4 v = X4[idx];
        __nv_bfloat162 h0 = __float22bfloat162_rn(make_float2(v.x, v.y));
        __nv_bfloat162 h1 = __float22bfloat162_rn(make_float2(v.z, v.w));
        uint2 o;
        o.x = *(unsigned*)&h0;
        o.y = *(unsigned*)&h1;
        out[idx] = o;
    }
}

// ---------------- init: deterministic pseudo-random unit vector ----------------
__global__ void k_init() {
    __shared__ float red[1024];
    int t = threadIdx.x;
    float vals[4];
    float ss = 0.f;
#pragma unroll
    for (int i = 0; i < 4; i++) {
        int j = t + i * 1024;
        unsigned h = (unsigned)j * 2654435761u;
        h ^= h >> 16; h *= 2246822519u; h ^= h >> 13;
        float x = (float)(h & 0xFFFFFF) * (1.0f / 16777216.0f) - 0.5f;
        vals[i] = x;
        ss += x * x;
    }
    red[t] = ss;
    __syncthreads();
    for (int s = 512; s > 0; s >>= 1) {
        if (t < s) red[t] += red[t + s];
        __syncthreads();
    }
    float inv = rsqrtf(red[0]);
#pragma unroll
    for (int i = 0; i < 4; i++) {
        int j = t + i * 1024;
        g_y[j] = vals[i] * inv;
        g_y[2 * NCOLS + j] = 0.f;
    }
    if (t < T_ITERS) g_ctr[t] = 0;
    if (t == 0) {
        for (int p = 0; p < REDB; p++) g_ss[p] = (p == 0) ? 1.f : 0.f;
    }
}

// ---------------- helpers ----------------
// partial dot of this thread's 16 bf16 columns with its 16 v registers
__device__ __forceinline__ float dot16(const uint4* rbk, const float* vr) {
    float a = 0.f;
#pragma unroll
    for (int p = 0; p < 2; p++) {
        uint4 xb = rbk[p];
        float2 f0 = __bfloat1622float2(*(__nv_bfloat162*)&xb.x);
        float2 f1 = __bfloat1622float2(*(__nv_bfloat162*)&xb.y);
        float2 f2 = __bfloat1622float2(*(__nv_bfloat162*)&xb.z);
        float2 f3 = __bfloat1622float2(*(__nv_bfloat162*)&xb.w);
        const float* v = vr + 8 * p;
        a += f0.x * v[0] + f0.y * v[1] + f1.x * v[2] + f1.y * v[3]
           + f2.x * v[4] + f2.y * v[5] + f3.x * v[6] + f3.y * v[7];
    }
    return a;
}

// ---------------- fused matvec + last-arrivals reduce ----------------
__global__ void __launch_bounds__(256, 2) k_matvec(int it) {
    __shared__ float upart[2][8];
    __shared__ float red[256];
    __shared__ float s_invn;
    __shared__ int s_ticket;
    __shared__ float4 sp[16][16];    // reducer slice tree
    __shared__ float s_scal[4];
    int t = threadIdx.x, b = blockIdx.x;
    int lane = t & 31, w = t >> 5;

    const float4* yv = (const float4*)(g_y + (it % 3) * NCOLS);
    const uint4* Xb = (const uint4*)(g_Xb + (size_t)b * RPB * NCOLS);

    // v registers: this thread's 16 columns [16t, 16t+16)
    float vr[16];
#pragma unroll
    for (int j = 0; j < 4; j++) {
        float4 vv = __ldg(&yv[4 * t + j]);
        vr[4 * j + 0] = vv.x; vr[4 * j + 1] = vv.y;
        vr[4 * j + 2] = vv.z; vr[4 * j + 3] = vv.w;
    }

    // register row buffers: 4 rows in flight, 2 uint4 (32B) each
    uint4 rb[4][2];
#pragma unroll
    for (int c = 0; c < 3; c++) {
        const uint4* src = Xb + (size_t)c * ROW_U4 + 2 * t;
        rb[c][0] = __ldg(src);
        rb[c][1] = __ldg(src + 1);
    }

    // invn = 1/||y|| from 64 partials (warp 0, overlapped with row loads)
    if (w == 0) {
        const float* sb = g_ss + it * REDB;
        float s = sb[lane] + sb[lane + 32];
#pragma unroll
        for (int o = 16; o > 0; o >>= 1) s += __shfl_down_sync(0xffffffffu, s, o);
        if (lane == 0) s_invn = rsqrtf(s);
    }

    float acc[16];
#pragma unroll
    for (int i = 0; i < 16; i++) acc[i] = 0.f;

    __syncthreads();
    float invn = s_invn;
    {
        float a0 = dot16(rb[0], vr);
#pragma unroll
        for (int o = 16; o > 0; o >>= 1) a0 += __shfl_down_sync(0xffffffffu, a0, o);
        if (lane == 0) upart[0][w] = a0;
    }

    for (int k = 0; k < NCHUNK; k++) {
        __syncthreads();   // publish upart[k&1]

        if (k + 3 < NCHUNK) {
            const uint4* src = Xb + (size_t)(k + 3) * ROW_U4 + 2 * t;
            rb[(k + 3) & 3][0] = __ldg(src);
            rb[(k + 3) & 3][1] = __ldg(src + 1);
        }

        if (k + 1 < NCHUNK) {
            float a0 = dot16(rb[(k + 1) & 3], vr);
#pragma unroll
            for (int o = 16; o > 0; o >>= 1) a0 += __shfl_down_sync(0xffffffffu, a0, o);
            if (lane == 0) upart[(k + 1) & 1][w] = a0;
        }

        // phase2(row k): acc += x_row * u_k
        {
            const float* up = upart[k & 1];
            float u0 = invn * (((up[0] + up[1]) + (up[2] + up[3]))
                             + ((up[4] + up[5]) + (up[6] + up[7])));
            const uint4* rk = rb[k & 3];
#pragma unroll
            for (int p = 0; p < 2; p++) {
                uint4 xb = rk[p];
                float2 f0 = __bfloat1622float2(*(__nv_bfloat162*)&xb.x);
                float2 f1 = __bfloat1622float2(*(__nv_bfloat162*)&xb.y);
                float2 f2 = __bfloat1622float2(*(__nv_bfloat162*)&xb.z);
                float2 f3 = __bfloat1622float2(*(__nv_bfloat162*)&xb.w);
                acc[8 * p + 0] += f0.x * u0; acc[8 * p + 1] += f0.y * u0;
                acc[8 * p + 2] += f1.x * u0; acc[8 * p + 3] += f1.y * u0;
                acc[8 * p + 4] += f2.x * u0; acc[8 * p + 5] += f2.y * u0;
                acc[8 * p + 6] += f3.x * u0; acc[8 * p + 7] += f3.y * u0;
            }
        }
    }

    // epilogue: write w partials (cols 16t..16t+16) + alpha partial
    float d = 0.f;
    float4* wp = (float4*)(g_wpart + (size_t)b * NCOLS);
#pragma unroll
    for (int j = 0; j < 4; j++) {
        float4 av = make_float4(acc[4 * j + 0], acc[4 * j + 1],
                                acc[4 * j + 2], acc[4 * j + 3]);
        wp[4 * t + j] = av;
        d += av.x * vr[4 * j + 0] + av.y * vr[4 * j + 1]
           + av.z * vr[4 * j + 2] + av.w * vr[4 * j + 3];
    }
    red[t] = d;
    __syncthreads();
    for (int s = 128; s > 0; s >>= 1) {
        if (t < s) red[t] += red[t + s];
        __syncthreads();
    }
    if (t == 0) g_dot[b] = red[0] * invn;

    // ---- publish and take ticket ----
    __threadfence();
    __syncthreads();
    if (t == 0) s_ticket = atomicAdd(&g_ctr[it], 1);
    __syncthreads();
    int ticket = s_ticket;
    if (ticket < NBLK - REDB) return;          // early finishers exit
    int rb_slot = ticket - (NBLK - REDB);      // reducer slot 0..63

    // ---- wait for all blocks (co-residency: 2 CTAs/SM x 148 = 296 >= 256) ----
    if (t == 0) {
        while (atomicAdd(&g_ctr[it], 0) < NBLK) { }
    }
    __syncthreads();
    __threadfence();

    // ---- reduce 64 columns (16 float4 groups) for this slot ----
    int cgl = t & 15;               // f4-group within slot
    int slice = t >> 4;             // 0..15, each sums 16 of 256 partials
    int cg = rb_slot * 16 + cgl;    // global f4-group 0..1023
    float4 wsum = make_float4(0.f, 0.f, 0.f, 0.f);
    {
        const float4* wpr = (const float4*)g_wpart + cg;
#pragma unroll
        for (int i = 0; i < 16; i++) {
            float4 v = wpr[(size_t)(slice * 16 + i) * (NCOLS / 4)];
            wsum.x += v.x; wsum.y += v.y; wsum.z += v.z; wsum.w += v.w;
        }
    }
    sp[slice][cgl] = wsum;

    // scalars: warp 0 -> alpha, warp 1 -> cur norm, warp 2 -> prev norm
    if (w == 0) {
        float dv = 0.f;
#pragma unroll
        for (int i = 0; i < 8; i++) dv += g_dot[lane + 32 * i];
#pragma unroll
        for (int o = 16; o > 0; o >>= 1) dv += __shfl_down_sync(0xffffffffu, dv, o);
        if (lane == 0) s_scal[0] = dv;
    } else if (w == 1) {
        const float* sb = g_ss + it * REDB;
        float nv = sb[lane] + sb[lane + 32];
#pragma unroll
        for (int o = 16; o > 0; o >>= 1) nv += __shfl_down_sync(0xffffffffu, nv, o);
        if (lane == 0) s_scal[1] = nv;
    } else if (w == 2) {
        float nv = 0.f;
        if (it > 0) {
            const float* sb = g_ss + (it - 1) * REDB;
            nv = sb[lane] + sb[lane + 32];
        }
#pragma unroll
        for (int o = 16; o > 0; o >>= 1) nv += __shfl_down_sync(0xffffffffu, nv, o);
        if (lane == 0) s_scal[2] = nv;
    }
    __syncthreads();

    // slice tree (fixed order)
    for (int s = 8; s > 0; s >>= 1) {
        if (slice < s) {
            float4 o = sp[slice + s][cgl];
            sp[slice][cgl].x += o.x; sp[slice][cgl].y += o.y;
            sp[slice][cgl].z += o.z; sp[slice][cgl].w += o.w;
        }
        __syncthreads();
    }

    if (t < 16) {   // 16 threads: one f4-group each
        float alpha = s_scal[0];
        float n = sqrtf(s_scal[1]);
        float ca = alpha / n;
        float cb = (it > 0) ? n * rsqrtf(s_scal[2]) : 0.f;

        float4 wv = sp[0][cgl];
        const float4* ycur = (const float4*)(g_y + (it % 3) * NCOLS);
        const float4* yprv = (const float4*)(g_y + ((it + 2) % 3) * NCOLS);
        float4* ynxt = (float4*)(g_y + ((it + 1) % 3) * NCOLS);
        float4 vc = ycur[cg], vp4 = yprv[cg];
        float4 yt;
        yt.x = wv.x - ca * vc.x - cb * vp4.x;
        yt.y = wv.y - ca * vc.y - cb * vp4.y;
        yt.z = wv.z - ca * vc.z - cb * vp4.z;
        yt.w = wv.w - ca * vc.w - cb * vp4.w;
        ynxt[cg] = yt;

        float nrm = yt.x * yt.x + yt.y * yt.y + yt.z * yt.z + yt.w * yt.w;
#pragma unroll
        for (int o = 8; o > 0; o >>= 1) nrm += __shfl_down_sync(0x0000ffffu, nrm, o);
        if (cgl == 0) {
            g_ss[(it + 1) * REDB + rb_slot] = nrm;
            if (rb_slot == 0) g_alpha[it] = alpha;
        }
    }
}

// ---------------- lambda_max of tridiagonal: warp-parallel Sturm bisection (fp64) ----------------
__global__ void k_tridiag(float* out) {
    __shared__ double a[T_ITERS], b2[T_ITERS];
    int lane = threadIdx.x;
    for (int i = lane; i < T_ITERS; i += 32) {
        a[i] = (double)g_alpha[i];
        double s = 0.0;
        if (i > 0) {
            for (int p = 0; p < REDB; p++) s += (double)g_ss[i * REDB + p];
        }
        b2[i] = s;
    }
    __syncwarp();

    double lo = 1e300, hi = -1e300;
    for (int i = lane; i < T_ITERS; i += 32) {
        double r = sqrt(b2[i]) + ((i + 1 < T_ITERS) ? sqrt(b2[i + 1]) : 0.0);
        lo = fmin(lo, a[i] - r);
        hi = fmax(hi, a[i] + r);
    }
#pragma unroll
    for (int o = 16; o > 0; o >>= 1) {
        lo = fmin(lo, __shfl_xor_sync(0xffffffffu, lo, o));
        hi = fmax(hi, __shfl_xor_sync(0xffffffffu, hi, o));
    }
    lo -= 1.0; hi += 1.0;

    for (int round = 0; round < 6; round++) {
        double wdt = (hi - lo) / 33.0;
        double x = lo + wdt * (double)(lane + 1);
        int cnt = 0;
        double d = a[0] - x;
        if (d == 0.0) d = -1e-300;
        if (d < 0.0) cnt++;
        for (int i = 1; i < T_ITERS; i++) {
            d = a[i] - x - b2[i] / d;
            if (d == 0.0) d = -1e-300;
            if (d < 0.0) cnt++;
        }
        unsigned m = __ballot_sync(0xffffffffu, cnt >= T_ITERS);
        if (m) {
            int f = __ffs(m) - 1;
            hi = lo + wdt * (double)(f + 1);
            lo = lo + wdt * (double)f;
        } else {
            lo = lo + wdt * 32.0;
        }
    }
    if (lane == 0) out[0] = (float)(0.5 * (lo + hi));
}

// ---------------- launch ----------------
extern "C" void kernel_launch(void* const* d_in, const int* in_sizes, int n_in,
                              void* d_out, int out_size) {
    const float* X = (const float*)d_in[0];
    float* out = (float*)d_out;

    k_tobf16<<<8192, 256>>>(X);
    k_init<<<1, 1024>>>();
    for (int it = 0; it < T_ITERS; it++) {
        k_matvec<<<NBLK, 256>>>(it);
    }
    k_tridiag<<<1, 32>>>(out);
}

// round 12
// speedup vs baseline: 1.1189x; 1.1189x over previous
#include <cuda_runtime.h>
#include <cuda_bf16.h>
#include <math.h>

#define MROWS 8192
#define NCOLS 4096
#define T_ITERS 40
#define NBLK 148               // persistent blocks = #SMs (1 CTA/SM)
#define ROW_U4 (NCOLS / 8)     // 512 uint4 per bf16 row
#define CHUNK_BYTES (NCOLS * 2)  // 8KB bf16 row
#define CHUNK_U4 (CHUNK_BYTES / 16)
#define NBUF 12
#define PF 10                  // chunks in flight
#define REDB 64                // reducer blocks (blockIdx < REDB)
#define SMEM_BYTES (NBUF * CHUNK_BYTES)  // 96KB

// ---------------- device scratch ----------------
__device__ __nv_bfloat16 g_Xb[(size_t)MROWS * NCOLS];
__device__ float g_y[3 * NCOLS];
__device__ float g_wpart[NBLK * NCOLS];
__device__ float g_dot[NBLK];
__device__ float g_ss[(T_ITERS + 1) * REDB];
__device__ float g_alpha[T_ITERS];
__device__ int   g_ctrA[T_ITERS];   // matvec done
__device__ int   g_ctrB[T_ITERS];   // reduce done

// row range of block b: 8192 = 148*55 + 52 -> blocks 0..51 have 56 rows
__device__ __forceinline__ int row_start(int b) { return 55 * b + min(b, 52); }

// ---------------- one-time fp32 -> bf16 conversion ----------------
__global__ void __launch_bounds__(256) k_tobf16(const float* __restrict__ X) {
    const float4* X4 = (const float4*)X;
    uint2* out = (uint2*)g_Xb;
    size_t base = (size_t)blockIdx.x * 1024 + threadIdx.x;
#pragma unroll
    for (int i = 0; i < 4; i++) {
        size_t idx = base + (size_t)i * 256;
        float4 v = X4[idx];
        __nv_bfloat162 h0 = __float22bfloat162_rn(make_float2(v.x, v.y));
        __nv_bfloat162 h1 = __float22bfloat162_rn(make_float2(v.z, v.w));
        uint2 o;
        o.x = *(unsigned*)&h0;
        o.y = *(unsigned*)&h1;
        out[idx] = o;
    }
}

// ---------------- init ----------------
__global__ void k_init() {
    __shared__ float red[1024];
    int t = threadIdx.x;
    float vals[4];
    float ss = 0.f;
#pragma unroll
    for (int i = 0; i < 4; i++) {
        int j = t + i * 1024;
        unsigned h = (unsigned)j * 2654435761u;
        h ^= h >> 16; h *= 2246822519u; h ^= h >> 13;
        float x = (float)(h & 0xFFFFFF) * (1.0f / 16777216.0f) - 0.5f;
        vals[i] = x;
        ss += x * x;
    }
    red[t] = ss;
    __syncthreads();
    for (int s = 512; s > 0; s >>= 1) {
        if (t < s) red[t] += red[t + s];
        __syncthreads();
    }
    float inv = rsqrtf(red[0]);
#pragma unroll
    for (int i = 0; i < 4; i++) {
        int j = t + i * 1024;
        g_y[j] = vals[i] * inv;
        g_y[2 * NCOLS + j] = 0.f;
    }
    if (t < T_ITERS) { g_ctrA[t] = 0; g_ctrB[t] = 0; }
    if (t == 0) {
        for (int p = 0; p < REDB; p++) g_ss[p] = (p == 0) ? 1.f : 0.f;
    }
}

// ---------------- streaming helpers (R9-proven) ----------------
__device__ __forceinline__ void prefetch_chunk(void* x_s, int slot, const uint4* src, int t) {
    unsigned base = (unsigned)__cvta_generic_to_shared((char*)x_s + slot * CHUNK_BYTES) + t * 16;
    asm volatile("cp.async.cg.shared.global [%0], [%1], 16;\n"
                 :: "r"(base), "l"(src + t) : "memory");
    asm volatile("cp.async.cg.shared.global [%0], [%1], 16;\n"
                 :: "r"(base + 4096), "l"(src + 256 + t) : "memory");
    asm volatile("cp.async.commit_group;\n" ::: "memory");
}

__device__ __forceinline__ float dot8(uint4 xb, float4 a, float4 b) {
    float2 f0 = __bfloat1622float2(*(__nv_bfloat162*)&xb.x);
    float2 f1 = __bfloat1622float2(*(__nv_bfloat162*)&xb.y);
    float2 f2 = __bfloat1622float2(*(__nv_bfloat162*)&xb.z);
    float2 f3 = __bfloat1622float2(*(__nv_bfloat162*)&xb.w);
    return f0.x * a.x + f0.y * a.y + f1.x * a.z + f1.y * a.w
         + f2.x * b.x + f2.y * b.y + f3.x * b.z + f3.y * b.w;
}

extern __shared__ uint4 x_s[];

__device__ __forceinline__ float p1_dot(const uint4* xs, const float4* yv, int lane, int w) {
    float a0 = 0.f;
#pragma unroll
    for (int i = 0; i < 2; i++) {
        int id = w * 64 + 32 * i + lane;
        uint4 xb = xs[id];
        float4 ya = __ldg(&yv[2 * id]);
        float4 yb = __ldg(&yv[2 * id + 1]);
        a0 += dot8(xb, ya, yb);
    }
#pragma unroll
    for (int o = 16; o > 0; o >>= 1) a0 += __shfl_down_sync(0xffffffffu, a0, o);
    return a0;
}

// ---------------- persistent Lanczos kernel ----------------
__global__ void __launch_bounds__(256, 1) k_lanczos() {
    __shared__ float upart[2][8];
    __shared__ float red[256];
    __shared__ float s_invn;
    __shared__ float4 sp[16][16];
    __shared__ float s_scal[4];
    int t = threadIdx.x, b = blockIdx.x;
    int lane = t & 31, w = t >> 5;

    int rs = row_start(b);
    int nrows = row_start(b + 1) - rs;       // 55 or 56 (>= PF+1)
    const uint4* Xb = (const uint4*)(g_Xb + (size_t)rs * NCOLS);
    float4* wp = (float4*)(g_wpart + (size_t)b * NCOLS);

    for (int it = 0; it < T_ITERS; it++) {
        const float4* yv = (const float4*)(g_y + (it % 3) * NCOLS);

        float acc[16];
#pragma unroll
        for (int i = 0; i < 16; i++) acc[i] = 0.f;

        // prologue: PF chunks in flight
#pragma unroll
        for (int c = 0; c < PF; c++) prefetch_chunk(x_s, c, Xb + (size_t)c * CHUNK_U4, t);

        // invn from 64 norm partials (warp 0, under prefetch latency)
        if (w == 0) {
            const float* sb = g_ss + it * REDB;
            float s = sb[lane] + sb[lane + 32];
#pragma unroll
            for (int o = 16; o > 0; o >>= 1) s += __shfl_down_sync(0xffffffffu, s, o);
            if (lane == 0) s_invn = rsqrtf(s);
        }

        asm volatile("cp.async.wait_group %0;\n" :: "n"(PF - 1) : "memory");
        __syncthreads();
        float invn = s_invn;
        {
            float a0 = p1_dot(x_s, yv, lane, w);
            if (lane == 0) upart[0][w] = a0;
        }

        for (int k = 0; k < nrows; k++) {
            if (k + 1 < nrows) {
                if (k + PF < nrows) {
                    asm volatile("cp.async.wait_group %0;\n" :: "n"(PF - 1) : "memory");
                } else {
                    asm volatile("cp.async.wait_group 0;\n" ::: "memory");
                }
            }
            __syncthreads();

            if (k + PF < nrows)
                prefetch_chunk(x_s, (k + PF) % NBUF, Xb + (size_t)(k + PF) * CHUNK_U4, t);

            if (k + 1 < nrows) {
                float a0 = p1_dot(x_s + ((k + 1) % NBUF) * CHUNK_U4, yv, lane, w);
                if (lane == 0) upart[(k + 1) & 1][w] = a0;
            }

            // phase2(row k)
            {
                const float* up = upart[k & 1];
                float u0 = invn * (((up[0] + up[1]) + (up[2] + up[3]))
                                 + ((up[4] + up[5]) + (up[6] + up[7])));
                const uint4* x0 = x_s + (k % NBUF) * CHUNK_U4 + t;
#pragma unroll
                for (int j = 0; j < 2; j++) {
                    uint4 xb = x0[256 * j];
                    float2 f0 = __bfloat1622float2(*(__nv_bfloat162*)&xb.x);
                    float2 f1 = __bfloat1622float2(*(__nv_bfloat162*)&xb.y);
                    float2 f2 = __bfloat1622float2(*(__nv_bfloat162*)&xb.z);
                    float2 f3 = __bfloat1622float2(*(__nv_bfloat162*)&xb.w);
                    acc[8 * j + 0] += f0.x * u0; acc[8 * j + 1] += f0.y * u0;
                    acc[8 * j + 2] += f1.x * u0; acc[8 * j + 3] += f1.y * u0;
                    acc[8 * j + 4] += f2.x * u0; acc[8 * j + 5] += f2.y * u0;
                    acc[8 * j + 6] += f3.x * u0; acc[8 * j + 7] += f3.y * u0;
                }
            }
        }

        // epilogue: wpart + alpha partial
        float d = 0.f;
#pragma unroll
        for (int j = 0; j < 2; j++) {
#pragma unroll
            for (int h = 0; h < 2; h++) {
                int fi = j * 512 + 2 * t + h;
                float4 av = make_float4(acc[8 * j + 4 * h + 0], acc[8 * j + 4 * h + 1],
                                        acc[8 * j + 4 * h + 2], acc[8 * j + 4 * h + 3]);
                wp[fi] = av;
                float4 vv = __ldg(&yv[fi]);
                d += av.x * vv.x + av.y * vv.y + av.z * vv.z + av.w * vv.w;
            }
        }
        red[t] = d;
        __syncthreads();
        for (int s = 128; s > 0; s >>= 1) {
            if (t < s) red[t] += red[t + s];
            __syncthreads();
        }
        if (t == 0) g_dot[b] = red[0] * invn;

        // ---- arrive A ----
        __threadfence();
        __syncthreads();
        if (t == 0) atomicAdd(&g_ctrA[it], 1);

        // ---- reducers: blocks 0..63 ----
        if (b < REDB) {
            if (t == 0) {
                while (atomicAdd(&g_ctrA[it], 0) < NBLK) __nanosleep(64);
            }
            __syncthreads();
            __threadfence();

            int cgl = t & 15;            // f4-group within slot
            int slice = t >> 4;          // 0..15
            int cg = b * 16 + cgl;       // global f4-group
            float4 wsum = make_float4(0.f, 0.f, 0.f, 0.f);
            {
                const float4* wpr = (const float4*)g_wpart + cg;
#pragma unroll
                for (int j = 0; j < 10; j++) {
                    int i = slice + 16 * j;
                    if (i < NBLK) {
                        float4 v = wpr[(size_t)i * (NCOLS / 4)];
                        wsum.x += v.x; wsum.y += v.y; wsum.z += v.z; wsum.w += v.w;
                    }
                }
            }
            sp[slice][cgl] = wsum;

            if (w == 0) {                // alpha over 148 dot partials
                float dv = 0.f;
#pragma unroll
                for (int j = 0; j < 5; j++) {
                    int i = lane + 32 * j;
                    if (i < NBLK) dv += g_dot[i];
                }
#pragma unroll
                for (int o = 16; o > 0; o >>= 1) dv += __shfl_down_sync(0xffffffffu, dv, o);
                if (lane == 0) s_scal[0] = dv;
            } else if (w == 1) {
                const float* sb = g_ss + it * REDB;
                float nv = sb[lane] + sb[lane + 32];
#pragma unroll
                for (int o = 16; o > 0; o >>= 1) nv += __shfl_down_sync(0xffffffffu, nv, o);
                if (lane == 0) s_scal[1] = nv;
            } else if (w == 2) {
                float nv = 0.f;
                if (it > 0) {
                    const float* sb = g_ss + (it - 1) * REDB;
                    nv = sb[lane] + sb[lane + 32];
                }
#pragma unroll
                for (int o = 16; o > 0; o >>= 1) nv += __shfl_down_sync(0xffffffffu, nv, o);
                if (lane == 0) s_scal[2] = nv;
            }
            __syncthreads();

            for (int s = 8; s > 0; s >>= 1) {
                if (slice < s) {
                    float4 o = sp[slice + s][cgl];
                    sp[slice][cgl].x += o.x; sp[slice][cgl].y += o.y;
                    sp[slice][cgl].z += o.z; sp[slice][cgl].w += o.w;
                }
                __syncthreads();
            }

            if (t < 16) {
                float alpha = s_scal[0];
                float n = sqrtf(s_scal[1]);
                float ca = alpha / n;
                float cb = (it > 0) ? n * rsqrtf(s_scal[2]) : 0.f;

                float4 wv = sp[0][cgl];
                const float4* ycur = (const float4*)(g_y + (it % 3) * NCOLS);
                const float4* yprv = (const float4*)(g_y + ((it + 2) % 3) * NCOLS);
                float4* ynxt = (float4*)(g_y + ((it + 1) % 3) * NCOLS);
                float4 vc = ycur[cg], vp4 = yprv[cg];
                float4 yt;
                yt.x = wv.x - ca * vc.x - cb * vp4.x;
                yt.y = wv.y - ca * vc.y - cb * vp4.y;
                yt.z = wv.z - ca * vc.z - cb * vp4.z;
                yt.w = wv.w - ca * vc.w - cb * vp4.w;
                ynxt[cg] = yt;

                float nrm = yt.x * yt.x + yt.y * yt.y + yt.z * yt.z + yt.w * yt.w;
#pragma unroll
                for (int o = 8; o > 0; o >>= 1) nrm += __shfl_down_sync(0x0000ffffu, nrm, o);
                if (cgl == 0) {
                    g_ss[(it + 1) * REDB + b] = nrm;
                    if (b == 0) g_alpha[it] = alpha;
                }
            }
            __threadfence();
            __syncthreads();
            if (t == 0) atomicAdd(&g_ctrB[it], 1);
        }

        // ---- all blocks wait for reduce done before next iteration ----
        if (it + 1 < T_ITERS) {
            if (t == 0) {
                while (atomicAdd(&g_ctrB[it], 0) < REDB) __nanosleep(64);
            }
            __syncthreads();
            __threadfence();
        }
    }
}

// ---------------- lambda_max of tridiagonal: warp-parallel Sturm bisection (fp64) ----------------
__global__ void k_tridiag(float* out) {
    __shared__ double a[T_ITERS], b2[T_ITERS];
    int lane = threadIdx.x;
    for (int i = lane; i < T_ITERS; i += 32) {
        a[i] = (double)g_alpha[i];
        double s = 0.0;
        if (i > 0) {
            for (int p = 0; p < REDB; p++) s += (double)g_ss[i * REDB + p];
        }
        b2[i] = s;
    }
    __syncwarp();

    double lo = 1e300, hi = -1e300;
    for (int i = lane; i < T_ITERS; i += 32) {
        double r = sqrt(b2[i]) + ((i + 1 < T_ITERS) ? sqrt(b2[i + 1]) : 0.0);
        lo = fmin(lo, a[i] - r);
        hi = fmax(hi, a[i] + r);
    }
#pragma unroll
    for (int o = 16; o > 0; o >>= 1) {
        lo = fmin(lo, __shfl_xor_sync(0xffffffffu, lo, o));
        hi = fmax(hi, __shfl_xor_sync(0xffffffffu, hi, o));
    }
    lo -= 1.0; hi += 1.0;

    for (int round = 0; round < 6; round++) {
        double wdt = (hi - lo) / 33.0;
        double x = lo + wdt * (double)(lane + 1);
        int cnt = 0;
        double d = a[0] - x;
        if (d == 0.0) d = -1e-300;
        if (d < 0.0) cnt++;
        for (int i = 1; i < T_ITERS; i++) {
            d = a[i] - x - b2[i] / d;
            if (d == 0.0) d = -1e-300;
            if (d < 0.0) cnt++;
        }
        unsigned m = __ballot_sync(0xffffffffu, cnt >= T_ITERS);
        if (m) {
            int f = __ffs(m) - 1;
            hi = lo + wdt * (double)(f + 1);
            lo = lo + wdt * (double)f;
        } else {
            lo = lo + wdt * 32.0;
        }
    }
    if (lane == 0) out[0] = (float)(0.5 * (lo + hi));
}

// ---------------- launch ----------------
extern "C" void kernel_launch(void* const* d_in, const int* in_sizes, int n_in,
                              void* d_out, int out_size) {
    const float* X = (const float*)d_in[0];
    float* out = (float*)d_out;

    cudaFuncSetAttribute(k_lanczos, cudaFuncAttributeMaxDynamicSharedMemorySize, SMEM_BYTES);

    k_tobf16<<<8192, 256>>>(X);
    k_init<<<1, 1024>>>();
    k_lanczos<<<NBLK, 256, SMEM_BYTES>>>();
    k_tridiag<<<1, 32>>>(out);
}

// round 13
// speedup vs baseline: 1.3079x; 1.1689x over previous
#include <cuda_runtime.h>
#include <cuda_bf16.h>
#include <math.h>

#define MROWS 8192
#define NCOLS 4096
#define T_ITERS 40
#define NBLK 256               // matvec blocks
#define RPB 32                 // rows per matvec block
#define NCHUNK 32              // 1 row per chunk
#define CHUNK_BYTES (NCOLS * 2)        // 8KB (bf16 row)
#define CHUNK_U4 (CHUNK_BYTES / 16)    // 512 uint4
#define NBUF 6
#define REDB 64                // reducer slots (last arrivals) = norm partials
#define SMEM_BYTES (NBUF * CHUNK_BYTES)  // 48KB

// ---------------- device scratch ----------------
__device__ __nv_bfloat16 g_Xb[(size_t)MROWS * NCOLS];  // 67MB bf16 copy of X
__device__ float g_y[3 * NCOLS];
__device__ float g_wpart[NBLK * NCOLS];
__device__ float g_dot[NBLK];
__device__ float g_ss[(T_ITERS + 1) * REDB];
__device__ float g_alpha[T_ITERS];
__device__ int   g_ctr[T_ITERS];

// ---------------- one-time fp32 -> bf16 conversion ----------------
__global__ void __launch_bounds__(256) k_tobf16(const float* __restrict__ X) {
    const float4* X4 = (const float4*)X;
    uint2* out = (uint2*)g_Xb;
    size_t base = (size_t)blockIdx.x * 1024 + threadIdx.x;
#pragma unroll
    for (int i = 0; i < 4; i++) {
        size_t idx = base + (size_t)i * 256;
        float4 v = X4[idx];
        __nv_bfloat162 h0 = __float22bfloat162_rn(make_float2(v.x, v.y));
        __nv_bfloat162 h1 = __float22bfloat162_rn(make_float2(v.z, v.w));
        uint2 o;
        o.x = *(unsigned*)&h0;
        o.y = *(unsigned*)&h1;
        out[idx] = o;
    }
}

// ---------------- init: deterministic pseudo-random unit vector ----------------
__global__ void k_init() {
    __shared__ float red[1024];
    int t = threadIdx.x;
    float vals[4];
    float ss = 0.f;
#pragma unroll
    for (int i = 0; i < 4; i++) {
        int j = t + i * 1024;
        unsigned h = (unsigned)j * 2654435761u;
        h ^= h >> 16; h *= 2246822519u; h ^= h >> 13;
        float x = (float)(h & 0xFFFFFF) * (1.0f / 16777216.0f) - 0.5f;
        vals[i] = x;
        ss += x * x;
    }
    red[t] = ss;
    __syncthreads();
    for (int s = 512; s > 0; s >>= 1) {
        if (t < s) red[t] += red[t + s];
        __syncthreads();
    }
    float inv = rsqrtf(red[0]);
#pragma unroll
    for (int i = 0; i < 4; i++) {
        int j = t + i * 1024;
        g_y[j] = vals[i] * inv;
        g_y[2 * NCOLS + j] = 0.f;
    }
    if (t < T_ITERS) g_ctr[t] = 0;
    if (t == 0) {
        for (int p = 0; p < REDB; p++) g_ss[p] = (p == 0) ? 1.f : 0.f;
    }
}

// ---------------- fused matvec + last-arrivals reduce (R9-proven) ----------------
__device__ __forceinline__ void prefetch_chunk(void* x_s, int slot, const uint4* src, int t) {
    unsigned base = (unsigned)__cvta_generic_to_shared((char*)x_s + slot * CHUNK_BYTES) + t * 16;
    asm volatile("cp.async.cg.shared.global [%0], [%1], 16;\n"
                 :: "r"(base), "l"(src + t) : "memory");
    asm volatile("cp.async.cg.shared.global [%0], [%1], 16;\n"
                 :: "r"(base + 4096), "l"(src + 256 + t) : "memory");
    asm volatile("cp.async.commit_group;\n" ::: "memory");
}

__device__ __forceinline__ float dot8(uint4 xb, float4 a, float4 b) {
    float2 f0 = __bfloat1622float2(*(__nv_bfloat162*)&xb.x);
    float2 f1 = __bfloat1622float2(*(__nv_bfloat162*)&xb.y);
    float2 f2 = __bfloat1622float2(*(__nv_bfloat162*)&xb.z);
    float2 f3 = __bfloat1622float2(*(__nv_bfloat162*)&xb.w);
    return f0.x * a.x + f0.y * a.y + f1.x * a.z + f1.y * a.w
         + f2.x * b.x + f2.y * b.y + f3.x * b.z + f3.y * b.w;
}

extern __shared__ uint4 x_s[];

__device__ __forceinline__ float p1_dot(const uint4* xs, const float4* yv, int lane, int w) {
    float a0 = 0.f;
#pragma unroll
    for (int i = 0; i < 2; i++) {
        int id = w * 64 + 32 * i + lane;
        uint4 xb = xs[id];
        float4 ya = __ldg(&yv[2 * id]);
        float4 yb = __ldg(&yv[2 * id + 1]);
        a0 += dot8(xb, ya, yb);
    }
#pragma unroll
    for (int o = 16; o > 0; o >>= 1) a0 += __shfl_down_sync(0xffffffffu, a0, o);
    return a0;
}

__global__ void __launch_bounds__(256, 3) k_matvec(int it) {
    __shared__ float upart[2][8];
    __shared__ float red[256];
    __shared__ float s_invn;
    __shared__ int s_ticket;
    __shared__ float4 sp[16][16];
    __shared__ float s_scal[4];
    int t = threadIdx.x, b = blockIdx.x;
    int lane = t & 31, w = t >> 5;

    const float4* yv = (const float4*)(g_y + (it % 3) * NCOLS);
    const uint4* Xb = (const uint4*)(g_Xb + (size_t)b * RPB * NCOLS);

    float acc[16];
#pragma unroll
    for (int i = 0; i < 16; i++) acc[i] = 0.f;

#pragma unroll
    for (int c = 0; c < 5; c++) prefetch_chunk(x_s, c, Xb + (size_t)c * CHUNK_U4, t);

    if (w == 0) {
        const float* sb = g_ss + it * REDB;
        float s = sb[lane] + sb[lane + 32];
#pragma unroll
        for (int o = 16; o > 0; o >>= 1) s += __shfl_down_sync(0xffffffffu, s, o);
        if (lane == 0) s_invn = rsqrtf(s);
    }

    asm volatile("cp.async.wait_group 4;\n" ::: "memory");
    __syncthreads();
    float invn = s_invn;
    {
        float a0 = p1_dot(x_s, yv, lane, w);
        if (lane == 0) upart[0][w] = a0;
    }

    for (int k = 0; k < NCHUNK; k++) {
        if (k + 1 < NCHUNK) {
            if (k + 4 < NCHUNK) {
                asm volatile("cp.async.wait_group 3;\n" ::: "memory");
            } else {
                asm volatile("cp.async.wait_group 0;\n" ::: "memory");
            }
        }
        __syncthreads();

        if (k + 5 < NCHUNK)
            prefetch_chunk(x_s, (k + 5) % NBUF, Xb + (size_t)(k + 5) * CHUNK_U4, t);

        if (k + 1 < NCHUNK) {
            float a0 = p1_dot(x_s + ((k + 1) % NBUF) * CHUNK_U4, yv, lane, w);
            if (lane == 0) upart[(k + 1) & 1][w] = a0;
        }

        {
            const float* up = upart[k & 1];
            float u0 = invn * (((up[0] + up[1]) + (up[2] + up[3]))
                             + ((up[4] + up[5]) + (up[6] + up[7])));
            const uint4* x0 = x_s + (k % NBUF) * CHUNK_U4 + t;
#pragma unroll
            for (int j = 0; j < 2; j++) {
                uint4 xb = x0[256 * j];
                float2 f0 = __bfloat1622float2(*(__nv_bfloat162*)&xb.x);
                float2 f1 = __bfloat1622float2(*(__nv_bfloat162*)&xb.y);
                float2 f2 = __bfloat1622float2(*(__nv_bfloat162*)&xb.z);
                float2 f3 = __bfloat1622float2(*(__nv_bfloat162*)&xb.w);
                acc[8 * j + 0] += f0.x * u0; acc[8 * j + 1] += f0.y * u0;
                acc[8 * j + 2] += f1.x * u0; acc[8 * j + 3] += f1.y * u0;
                acc[8 * j + 4] += f2.x * u0; acc[8 * j + 5] += f2.y * u0;
                acc[8 * j + 6] += f3.x * u0; acc[8 * j + 7] += f3.y * u0;
            }
        }
    }

    // epilogue: write w partials + alpha partial
    float d = 0.f;
    float4* wp = (float4*)(g_wpart + (size_t)b * NCOLS);
#pragma unroll
    for (int j = 0; j < 2; j++) {
#pragma unroll
        for (int h = 0; h < 2; h++) {
            int fi = j * 512 + 2 * t + h;
            float4 av = make_float4(acc[8 * j + 4 * h + 0], acc[8 * j + 4 * h + 1],
                                    acc[8 * j + 4 * h + 2], acc[8 * j + 4 * h + 3]);
            wp[fi] = av;
            float4 vv = __ldg(&yv[fi]);
            d += av.x * vv.x + av.y * vv.y + av.z * vv.z + av.w * vv.w;
        }
    }
    red[t] = d;
    __syncthreads();
    for (int s = 128; s > 0; s >>= 1) {
        if (t < s) red[t] += red[t + s];
        __syncthreads();
    }
    if (t == 0) g_dot[b] = red[0] * invn;

    // ---- publish and take ticket ----
    __threadfence();
    __syncthreads();
    if (t == 0) s_ticket = atomicAdd(&g_ctr[it], 1);
    __syncthreads();
    int ticket = s_ticket;
    if (ticket < NBLK - REDB) return;
    int rb = ticket - (NBLK - REDB);

    if (t == 0) {
        while (atomicAdd(&g_ctr[it], 0) < NBLK) { }
    }
    __syncthreads();
    __threadfence();

    // ---- reduce 64 columns (16 float4 groups) for this slot ----
    int cgl = t & 15;
    int slice = t >> 4;
    int cg = rb * 16 + cgl;
    float4 wsum = make_float4(0.f, 0.f, 0.f, 0.f);
    {
        const float4* wpr = (const float4*)g_wpart + cg;
#pragma unroll
        for (int i = 0; i < 16; i++) {
            float4 v = wpr[(size_t)(slice * 16 + i) * (NCOLS / 4)];
            wsum.x += v.x; wsum.y += v.y; wsum.z += v.z; wsum.w += v.w;
        }
    }
    sp[slice][cgl] = wsum;

    if (w == 0) {
        float dv = 0.f;
#pragma unroll
        for (int i = 0; i < 8; i++) dv += g_dot[lane + 32 * i];
#pragma unroll
        for (int o = 16; o > 0; o >>= 1) dv += __shfl_down_sync(0xffffffffu, dv, o);
        if (lane == 0) s_scal[0] = dv;
    } else if (w == 1) {
        const float* sb = g_ss + it * REDB;
        float nv = sb[lane] + sb[lane + 32];
#pragma unroll
        for (int o = 16; o > 0; o >>= 1) nv += __shfl_down_sync(0xffffffffu, nv, o);
        if (lane == 0) s_scal[1] = nv;
    } else if (w == 2) {
        float nv = 0.f;
        if (it > 0) {
            const float* sb = g_ss + (it - 1) * REDB;
            nv = sb[lane] + sb[lane + 32];
        }
#pragma unroll
        for (int o = 16; o > 0; o >>= 1) nv += __shfl_down_sync(0xffffffffu, nv, o);
        if (lane == 0) s_scal[2] = nv;
    }
    __syncthreads();

    for (int s = 8; s > 0; s >>= 1) {
        if (slice < s) {
            float4 o = sp[slice + s][cgl];
            sp[slice][cgl].x += o.x; sp[slice][cgl].y += o.y;
            sp[slice][cgl].z += o.z; sp[slice][cgl].w += o.w;
        }
        __syncthreads();
    }

    if (t < 16) {
        float alpha = s_scal[0];
        float n = sqrtf(s_scal[1]);
        float ca = alpha / n;
        float cb = (it > 0) ? n * rsqrtf(s_scal[2]) : 0.f;

        float4 wv = sp[0][cgl];
        const float4* ycur = (const float4*)(g_y + (it % 3) * NCOLS);
        const float4* yprv = (const float4*)(g_y + ((it + 2) % 3) * NCOLS);
        float4* ynxt = (float4*)(g_y + ((it + 1) % 3) * NCOLS);
        float4 vc = ycur[cg], vp4 = yprv[cg];
        float4 yt;
        yt.x = wv.x - ca * vc.x - cb * vp4.x;
        yt.y = wv.y - ca * vc.y - cb * vp4.y;
        yt.z = wv.z - ca * vc.z - cb * vp4.z;
        yt.w = wv.w - ca * vc.w - cb * vp4.w;
        ynxt[cg] = yt;

        float nrm = yt.x * yt.x + yt.y * yt.y + yt.z * yt.z + yt.w * yt.w;
#pragma unroll
        for (int o = 8; o > 0; o >>= 1) nrm += __shfl_down_sync(0x0000ffffu, nrm, o);
        if (cgl == 0) {
            g_ss[(it + 1) * REDB + rb] = nrm;
            if (rb == 0) g_alpha[it] = alpha;
        }
    }
}

// ---------------- lambda_max of tridiagonal: fp32 warp-parallel Sturm bisection ----------------
__global__ void k_tridiag(float* out) {
    __shared__ float a[T_ITERS], b2[T_ITERS];
    int lane = threadIdx.x;
    for (int i = lane; i < T_ITERS; i += 32) {
        a[i] = g_alpha[i];
        float s = 0.f;
        if (i > 0) {
            for (int p = 0; p < REDB; p++) s += g_ss[i * REDB + p];
        }
        b2[i] = s;  // beta_i^2 couples rows i-1, i
    }
    __syncwarp();

    float lo = 1e30f, hi = -1e30f;
    for (int i = lane; i < T_ITERS; i += 32) {
        float r = sqrtf(b2[i]) + ((i + 1 < T_ITERS) ? sqrtf(b2[i + 1]) : 0.f);
        lo = fminf(lo, a[i] - r);
        hi = fmaxf(hi, a[i] + r);
    }
#pragma unroll
    for (int o = 16; o > 0; o >>= 1) {
        lo = fminf(lo, __shfl_xor_sync(0xffffffffu, lo, o));
        hi = fmaxf(hi, __shfl_xor_sync(0xffffffffu, hi, o));
    }
    lo -= 1.f; hi += 1.f;

    for (int round = 0; round < 6; round++) {
        float wdt = (hi - lo) * (1.0f / 33.0f);
        float x = lo + wdt * (float)(lane + 1);
        int cnt = 0;
        float d = a[0] - x;
        if (d == 0.f) d = -1e-30f;
        if (d < 0.f) cnt++;
#pragma unroll 4
        for (int i = 1; i < T_ITERS; i++) {
            d = a[i] - x - __fdividef(b2[i], d);
            if (d == 0.f) d = -1e-30f;
            if (d < 0.f) cnt++;
        }
        unsigned m = __ballot_sync(0xffffffffu, cnt >= T_ITERS);
        if (m) {
            int f = __ffs(m) - 1;
            hi = lo + wdt * (float)(f + 1);
            lo = lo + wdt * (float)f;
        } else {
            lo = lo + wdt * 32.f;
        }
    }
    if (lane == 0) out[0] = 0.5f * (lo + hi);   // sigma_1^2
}

// ---------------- launch ----------------
extern "C" void kernel_launch(void* const* d_in, const int* in_sizes, int n_in,
                              void* d_out, int out_size) {
    const float* X = (const float*)d_in[0];
    float* out = (float*)d_out;

    cudaFuncSetAttribute(k_matvec, cudaFuncAttributeMaxDynamicSharedMemorySize, SMEM_BYTES);

    k_tobf16<<<8192, 256>>>(X);
    k_init<<<1, 1024>>>();
    for (int it = 0; it < T_ITERS; it++) {
        k_matvec<<<NBLK, 256, SMEM_BYTES>>>(it);
    }
    k_tridiag<<<1, 32>>>(out);
}